// round 13
// baseline (speedup 1.0000x reference)
#include <cuda_runtime.h>
#include <cuda_bf16.h>
#include <math_constants.h>
#include <cstdint>

#define N_NODES 50000
#define HID     128
#define E_EDGES 640000
#define ATT_SLOPE 0.2f
#define OUT_SLOPE 0.01f

// ---------------- scratch (device globals; no allocation allowed) ----------
__device__ float g_xl[N_NODES * HID];
__device__ float g_xr[N_NODES * HID];
__device__ float g_xl2[N_NODES * HID];
__device__ float g_xr2[N_NODES * HID];
__device__ float g_h1[N_NODES * HID];
__device__ int   g_deg[N_NODES];          // zero-init at load; re-zeroed by k_scan
__device__ int   g_rowptr[N_NODES + 1];
__device__ int   g_cursor[N_NODES];
__device__ int   g_esrc[E_EDGES];
__device__ uint32_t g_xhi[N_NODES * 64];
__device__ uint32_t g_xlo[N_NODES * 64];
__device__ uint32_t g_w1hi[256 * 64];
__device__ uint32_t g_w1lo[256 * 64];
__device__ uint32_t g_w2hi[256 * 64];
__device__ uint32_t g_w2lo[256 * 64];

__device__ __forceinline__ float lrelu(float x, float s) { return x > 0.f ? x : s * x; }

__device__ __forceinline__ uint32_t s2u(const void* p) {
    uint32_t a;
    asm("{ .reg .u64 t; cvta.to.shared.u64 t, %1; cvt.u32.u64 %0, t; }" : "=r"(a) : "l"(p));
    return a;
}
__device__ __forceinline__ void cpasync16(uint32_t dst, const void* src) {
    asm volatile("cp.async.cg.shared.global [%0], [%1], 16;" :: "r"(dst), "l"(src));
}
__device__ __forceinline__ void cpasync16p(uint32_t dst, const void* src, int sz) {
    asm volatile("cp.async.cg.shared.global [%0], [%1], 16, %2;"
                 :: "r"(dst), "l"(src), "r"(sz));
}

// ---------------- CSR build -------------------------------------------------
__global__ void k_hist(const int* __restrict__ dst) {
    int i = blockIdx.x * blockDim.x + threadIdx.x;
    if (i < E_EDGES) atomicAdd(&g_deg[dst[i]], 1);
}
// scan + cursor init + deg re-zero (deg dead after this kernel)
__global__ void __launch_bounds__(1024) k_scan() {
    __shared__ int ssum[1024];
    const int t = threadIdx.x;
    const int CH = (N_NODES + 1023) / 1024;
    const int base = t * CH;
    int s = 0;
    for (int j = 0; j < CH; j++) { int idx = base + j; if (idx < N_NODES) s += g_deg[idx]; }
    ssum[t] = s;
    __syncthreads();
    for (int off = 1; off < 1024; off <<= 1) {
        int v = (t >= off) ? ssum[t - off] : 0;
        __syncthreads();
        ssum[t] += v;
        __syncthreads();
    }
    int run = (t == 0) ? 0 : ssum[t - 1];
    for (int j = 0; j < CH; j++) {
        int idx = base + j;
        if (idx < N_NODES) {
            int d = g_deg[idx];
            g_rowptr[idx] = run;
            g_cursor[idx] = run;
            run += d;
            g_deg[idx] = 0;              // ready for next call's k_hist
        }
    }
    if (t == 1023) g_rowptr[N_NODES] = ssum[1023];
}
__global__ void k_scatter(const int* __restrict__ src, const int* __restrict__ dst) {
    int i = blockIdx.x * blockDim.x + threadIdx.x;
    if (i < E_EDGES) {
        int p = atomicAdd(&g_cursor[dst[i]], 1);
        g_esrc[p] = src[i];
    }
}

// ---------------- bf16 split helpers ----------------------------------------
__device__ __forceinline__ uint32_t pack_hi(float x, float y) {
    __nv_bfloat16 hx = __float2bfloat16(x), hy = __float2bfloat16(y);
    return ((uint32_t)__bfloat16_as_ushort(hy) << 16) | __bfloat16_as_ushort(hx);
}
__device__ __forceinline__ uint32_t pack_lo(float x, float y) {
    __nv_bfloat16 hx = __float2bfloat16(x), hy = __float2bfloat16(y);
    __nv_bfloat16 lx = __float2bfloat16(x - __bfloat162float(hx));
    __nv_bfloat16 ly = __float2bfloat16(y - __bfloat162float(hy));
    return ((uint32_t)__bfloat16_as_ushort(ly) << 16) | __bfloat16_as_ushort(lx);
}

// fused prep: X image (12500 blocks) + W1 image (64) + W2 image (64)
#define PX_BLOCKS 12500
#define W_BLOCKS  64
__global__ void k_prep(const float* __restrict__ X,
                       const float* __restrict__ wl1, const float* __restrict__ wr1,
                       const float* __restrict__ wl2, const float* __restrict__ wr2) {
    const int blk = blockIdx.x;
    if (blk < PX_BLOCKS) {
        int i = blk * 256 + threadIdx.x;          // < N_NODES*64 exactly
        float2 v = *(const float2*)(X + (size_t)i * 2);
        g_xhi[i] = pack_hi(v.x, v.y);
        g_xlo[i] = pack_lo(v.x, v.y);
    } else {
        const int wsel = (blk - PX_BLOCKS) / W_BLOCKS;   // 0 -> W1, 1 -> W2
        int i = ((blk - PX_BLOCKS) % W_BLOCKS) * 256 + threadIdx.x;  // < 256*64
        int n = i >> 6, p = i & 63;
        const float* wl = wsel ? wl2 : wl1;
        const float* wr = wsel ? wr2 : wr1;
        const float* wp = ((n < 128) ? wl : wr) + (size_t)(n & 127) * 128 + p * 2;
        float2 v = *(const float2*)wp;
        uint32_t* hi = wsel ? g_w2hi : g_w1hi;
        uint32_t* lo = wsel ? g_w2lo : g_w1lo;
        hi[i] = pack_hi(v.x, v.y);
        lo[i] = pack_lo(v.x, v.y);
    }
}

// ---------------- split-bf16 HMMA GEMM, M=64 x N=64 tiles, 3 CTAs/SM --------
#define LDP   136
#define SMEM_AHI 0
#define SMEM_ALO (SMEM_AHI + 64 * LDP * 2)   // 17408
#define SMEM_BHI (SMEM_ALO + 64 * LDP * 2)   // 34816
#define SMEM_BLO (SMEM_BHI + 64 * LDP * 2)   // 52224
#define SMEM_TOT (SMEM_BLO + 64 * LDP * 2)   // 69632

__device__ __forceinline__ void ldsm4(uint32_t& r0, uint32_t& r1, uint32_t& r2,
                                      uint32_t& r3, uint32_t addr) {
    asm volatile("ldmatrix.sync.aligned.m8n8.x4.shared.b16 {%0,%1,%2,%3}, [%4];"
                 : "=r"(r0), "=r"(r1), "=r"(r2), "=r"(r3) : "r"(addr));
}
__device__ __forceinline__ void mma16816(float* c, const uint32_t* a, const uint32_t* b) {
    asm volatile(
        "mma.sync.aligned.m16n8k16.row.col.f32.bf16.bf16.f32 "
        "{%0,%1,%2,%3}, {%4,%5,%6,%7}, {%8,%9}, {%0,%1,%2,%3};"
        : "+f"(c[0]), "+f"(c[1]), "+f"(c[2]), "+f"(c[3])
        : "r"(a[0]), "r"(a[1]), "r"(a[2]), "r"(a[3]), "r"(b[0]), "r"(b[1]));
}

__global__ void __launch_bounds__(256, 3)
k_gemm_tc(const uint32_t* __restrict__ whi, const uint32_t* __restrict__ wlo,
          float* __restrict__ out_l, float* __restrict__ out_r) {
    extern __shared__ char smem[];
    const uint32_t sb = s2u(smem);
    const int tid  = threadIdx.x;
    const int warp = tid >> 5;
    const int lane = tid & 31;
    const int mblk = blockIdx.x >> 2;        // 64-row slab
    const int nblk = blockIdx.x & 3;         // 64-col slab of 256

    // ---- stage A (64 rows, hi+lo, predicated) + B (64 rows, hi+lo) ----
    for (int c = tid; c < 1024; c += 256) {
        int row = c >> 4, seg = c & 15;
        long grow = (long)mblk * 64 + row;
        int sz = (grow < N_NODES) ? 16 : 0;
        uint32_t doff = (uint32_t)(row * (LDP * 2) + seg * 16);
        size_t soff = (size_t)grow * 256 + seg * 16;
        cpasync16p(sb + SMEM_AHI + doff, (const char*)g_xhi + soff, sz);
        cpasync16p(sb + SMEM_ALO + doff, (const char*)g_xlo + soff, sz);
    }
    {
        const char* bh = (const char*)(whi + (size_t)nblk * 64 * 64);
        const char* bl = (const char*)(wlo + (size_t)nblk * 64 * 64);
        for (int c = tid; c < 1024; c += 256) {
            int row = c >> 4, seg = c & 15;
            uint32_t doff = (uint32_t)(row * (LDP * 2) + seg * 16);
            uint32_t soff = (uint32_t)(row * 256 + seg * 16);
            cpasync16(sb + SMEM_BHI + doff, bh + soff);
            cpasync16(sb + SMEM_BLO + doff, bl + soff);
        }
    }
    asm volatile("cp.async.commit_group;" ::: "memory");
    asm volatile("cp.async.wait_group 0;" ::: "memory");
    __syncthreads();

    // ---- compute: 8 warps as 4M x 2N, warp tile 16x32 ----
    const int wm = (warp >> 1) * 16;
    const int wn = (warp & 1) * 32;
    float c[4][4];
#pragma unroll
    for (int ni = 0; ni < 4; ni++)
#pragma unroll
        for (int q = 0; q < 4; q++) c[ni][q] = 0.f;

    const uint32_t aRowOff = (uint32_t)((wm + (lane & 15)) * LDP + ((lane >> 4) << 3)) << 1;
    const uint32_t bRowOff = (uint32_t)((wn + ((lane >> 4) << 3) + (lane & 7)) * LDP
                                        + (((lane >> 3) & 1) << 3)) << 1;

#pragma unroll
    for (int term = 0; term < 3; term++) {
        const uint32_t Ab = sb + (term == 2 ? SMEM_ALO : SMEM_AHI) + aRowOff;
        const uint32_t Bb = sb + (term == 1 ? SMEM_BLO : SMEM_BHI) + bRowOff;
#pragma unroll
        for (int k0 = 0; k0 < 128; k0 += 16) {
            uint32_t a[4];
            ldsm4(a[0], a[1], a[2], a[3], Ab + (k0 << 1));
            uint32_t b[4][2];
#pragma unroll
            for (int nq = 0; nq < 2; nq++) {
                uint32_t r0, r1, r2, r3;
                ldsm4(r0, r1, r2, r3, Bb + ((nq * 16 * LDP) << 1) + (k0 << 1));
                b[nq * 2][0] = r0; b[nq * 2][1] = r1;
                b[nq * 2 + 1][0] = r2; b[nq * 2 + 1][1] = r3;
            }
#pragma unroll
            for (int ni = 0; ni < 4; ni++)
                mma16816(c[ni], a, b[ni]);
        }
    }

    // ---- epilogue: logical cols [nblk*64 + wn, +32) ----
    float* buf = (nblk < 2) ? out_l : out_r;
    const int colbase = ((nblk * 64) & 127) + wn + (lane & 3) * 2;
#pragma unroll
    for (int half = 0; half < 2; half++) {
        long row = (long)mblk * 64 + wm + (lane >> 2) + half * 8;
        if (row >= N_NODES) continue;
        float* rp = buf + row * HID + colbase;
#pragma unroll
        for (int ni = 0; ni < 4; ni++) {
            float2 v = make_float2(c[ni][half * 2], c[ni][half * 2 + 1]);
            *(float2*)(rp + ni * 8) = v;
        }
    }
}

// ---------------- fused per-node attention (exact R7 body) ------------------
template <int LAYER>
__global__ void k_node(const float* __restrict__ att, const float* __restrict__ b,
                       const float* __restrict__ xlbuf, const float* __restrict__ xrbuf,
                       float* __restrict__ outbuf) {
    const int n    = (blockIdx.x * blockDim.x + threadIdx.x) >> 5;
    const int lane = threadIdx.x & 31;
    if (n >= N_NODES) return;

    const int beg = g_rowptr[n];
    const int end = g_rowptr[n + 1];

    const float4 xr = *(const float4*)(xrbuf + (size_t)n * HID + lane * 4);
    const float4 at = *(const float4*)(att + lane * 4);

    float4 acc = make_float4(0.f, 0.f, 0.f, 0.f);
    float  sum = 0.f;

    for (int i0 = beg; i0 < end; i0 += 32) {
        const int cnt = min(32, end - i0);
        int sid = (lane < cnt) ? g_esrc[i0 + lane] : 0;
        for (int j = 0; j < cnt; j++) {
            const int s = __shfl_sync(0xffffffffu, sid, j);
            const float4 xl = *(const float4*)(xlbuf + (size_t)s * HID + lane * 4);
            float p = lrelu(xl.x + xr.x, ATT_SLOPE) * at.x
                    + lrelu(xl.y + xr.y, ATT_SLOPE) * at.y
                    + lrelu(xl.z + xr.z, ATT_SLOPE) * at.z
                    + lrelu(xl.w + xr.w, ATT_SLOPE) * at.w;
            p += __shfl_xor_sync(0xffffffffu, p, 8);
            p += __shfl_xor_sync(0xffffffffu, p, 4);
            p += __shfl_xor_sync(0xffffffffu, p, 2);
            p += __shfl_xor_sync(0xffffffffu, p, 1);
            const float ex = __expf(p);
            sum += ex;
            acc.x = fmaf(ex, xl.x, acc.x);
            acc.y = fmaf(ex, xl.y, acc.y);
            acc.z = fmaf(ex, xl.z, acc.z);
            acc.w = fmaf(ex, xl.w, acc.w);
        }
    }

    const float inv = 1.f / (sum + 1e-16f);
    const float4 bb = *(const float4*)(b + lane * 4);
    float4 o;
    o.x = fmaf(acc.x, inv, bb.x);
    o.y = fmaf(acc.y, inv, bb.y);
    o.z = fmaf(acc.z, inv, bb.z);
    o.w = fmaf(acc.w, inv, bb.w);

    float* dstp = outbuf + (size_t)n * HID + lane * 4;
    if (LAYER == 1) {
        o.x = lrelu(o.x, OUT_SLOPE);
        o.y = lrelu(o.y, OUT_SLOPE);
        o.z = lrelu(o.z, OUT_SLOPE);
        o.w = lrelu(o.w, OUT_SLOPE);
        *(float4*)dstp = o;
        const size_t ib = (size_t)n * 64 + lane * 2;
        uint2 hi = make_uint2(pack_hi(o.x, o.y), pack_hi(o.z, o.w));
        uint2 lo = make_uint2(pack_lo(o.x, o.y), pack_lo(o.z, o.w));
        *(uint2*)(g_xhi + ib) = hi;
        *(uint2*)(g_xlo + ib) = lo;
    } else {
        const float4 h = *(const float4*)(g_h1 + (size_t)n * HID + lane * 4);
        o.x += h.x; o.y += h.y; o.z += h.z; o.w += h.w;
        *(float4*)dstp = o;
    }
}

// ---------------- launch ----------------
extern "C" void kernel_launch(void* const* d_in, const int* in_sizes, int n_in,
                              void* d_out, int out_size) {
    const float* x    = (const float*)d_in[0];
    const int*   ei   = (const int*)d_in[1];
    const float* wl1  = (const float*)d_in[2];
    const float* wr1  = (const float*)d_in[3];
    const float* att1 = (const float*)d_in[4];
    const float* b1   = (const float*)d_in[5];
    const float* wl2  = (const float*)d_in[6];
    const float* wr2  = (const float*)d_in[7];
    const float* att2 = (const float*)d_in[8];
    const float* b2   = (const float*)d_in[9];
    float* out = (float*)d_out;

    const int* src = ei;
    const int* dst = ei + E_EDGES;

    void *h1_ptr, *xl_p, *xr_p, *xl2_p, *xr2_p;
    cudaGetSymbolAddress(&h1_ptr, g_h1);
    cudaGetSymbolAddress(&xl_p, g_xl);
    cudaGetSymbolAddress(&xr_p, g_xr);
    cudaGetSymbolAddress(&xl2_p, g_xl2);
    cudaGetSymbolAddress(&xr2_p, g_xr2);
    void *w1hi, *w1lo, *w2hi, *w2lo;
    cudaGetSymbolAddress(&w1hi, g_w1hi);
    cudaGetSymbolAddress(&w1lo, g_w1lo);
    cudaGetSymbolAddress(&w2hi, g_w2hi);
    cudaGetSymbolAddress(&w2lo, g_w2lo);

    static cudaStream_t s1 = nullptr;
    static cudaEvent_t ev_fork = nullptr, ev_csr = nullptr;
    if (s1 == nullptr) {
        cudaStreamCreateWithFlags(&s1, cudaStreamNonBlocking);
        cudaEventCreateWithFlags(&ev_fork, cudaEventDisableTiming);
        cudaEventCreateWithFlags(&ev_csr, cudaEventDisableTiming);
    }

    cudaFuncSetAttribute(k_gemm_tc, cudaFuncAttributeMaxDynamicSharedMemorySize, SMEM_TOT);

    const int gemm_blocks = ((N_NODES + 63) / 64) * 4;      // 3128
    const int node_blocks = (N_NODES * 32 + 255) / 256;     // 6250
    const int e_blocks    = (E_EDGES + 255) / 256;

    // fork s1 FROM THE CAPTURE STREAM (required for graph capture), then:
    // s0: prep, gemm1(slot 4 incl. s1 launches), node1, gemm2, node2
    // s1: hist, scan, scatter — no data deps on prep/gemm1, fully overlapped
    cudaEventRecord(ev_fork, 0);
    cudaStreamWaitEvent(s1, ev_fork, 0);

    k_prep<<<PX_BLOCKS + 2 * W_BLOCKS, 256>>>(x, wl1, wr1, wl2, wr2);
    k_hist<<<e_blocks, 256, 0, s1>>>(dst);
    k_scan<<<1, 1024, 0, s1>>>();
    k_gemm_tc<<<gemm_blocks, 256, SMEM_TOT>>>((const uint32_t*)w1hi, (const uint32_t*)w1lo,
                                              (float*)xl_p, (float*)xr_p);
    k_scatter<<<e_blocks, 256, 0, s1>>>(src, dst);
    cudaEventRecord(ev_csr, s1);
    cudaStreamWaitEvent(0, ev_csr, 0);

    k_node<1><<<node_blocks, 256>>>(att1, b1, (const float*)xl_p, (const float*)xr_p,
                                    (float*)h1_ptr);
    k_gemm_tc<<<gemm_blocks, 256, SMEM_TOT>>>((const uint32_t*)w2hi, (const uint32_t*)w2lo,
                                              (float*)xl2_p, (float*)xr2_p);
    k_node<2><<<node_blocks, 256>>>(att2, b2, (const float*)xl2_p, (const float*)xr2_p, out);
}

// round 14
// speedup vs baseline: 1.6131x; 1.6131x over previous
#include <cuda_runtime.h>
#include <cuda_bf16.h>
#include <math_constants.h>
#include <cstdint>

#define N_NODES 50000
#define HID     128
#define E_EDGES 640000
#define ATT_SLOPE 0.2f
#define OUT_SLOPE 0.01f

// ---------------- scratch (device globals; no allocation allowed) ----------
__device__ float g_xl[N_NODES * HID];
__device__ float g_xr[N_NODES * HID];
__device__ float g_h1[N_NODES * HID];
__device__ int   g_deg[N_NODES];
__device__ int   g_rowptr[N_NODES + 1];
__device__ int   g_cursor[N_NODES];
__device__ int   g_esrc[E_EDGES];
__device__ uint32_t g_xhi[N_NODES * 64];
__device__ uint32_t g_xlo[N_NODES * 64];
__device__ uint32_t g_w1hi[256 * 64];
__device__ uint32_t g_w1lo[256 * 64];
__device__ uint32_t g_w2hi[256 * 64];
__device__ uint32_t g_w2lo[256 * 64];

__device__ __forceinline__ float lrelu(float x, float s) { return x > 0.f ? x : s * x; }

__device__ __forceinline__ uint32_t s2u(const void* p) {
    uint32_t a;
    asm("{ .reg .u64 t; cvta.to.shared.u64 t, %1; cvt.u32.u64 %0, t; }" : "=r"(a) : "l"(p));
    return a;
}
__device__ __forceinline__ void cpasync16(uint32_t dst, const void* src) {
    asm volatile("cp.async.cg.shared.global [%0], [%1], 16;" :: "r"(dst), "l"(src));
}
__device__ __forceinline__ void cpasync16p(uint32_t dst, const void* src, int sz) {
    asm volatile("cp.async.cg.shared.global [%0], [%1], 16, %2;"
                 :: "r"(dst), "l"(src), "r"(sz));
}

// ---------------- CSR build (R7-exact) ---------------------------------------
__global__ void k_zero_deg() {
    int i = blockIdx.x * blockDim.x + threadIdx.x;
    if (i < N_NODES) g_deg[i] = 0;
}
__global__ void k_hist(const int* __restrict__ dst) {
    int i = blockIdx.x * blockDim.x + threadIdx.x;
    if (i < E_EDGES) atomicAdd(&g_deg[dst[i]], 1);
}
__global__ void __launch_bounds__(1024) k_scan() {
    __shared__ int ssum[1024];
    const int t = threadIdx.x;
    const int CH = (N_NODES + 1023) / 1024;
    const int base = t * CH;
    int s = 0;
    for (int j = 0; j < CH; j++) { int idx = base + j; if (idx < N_NODES) s += g_deg[idx]; }
    ssum[t] = s;
    __syncthreads();
    for (int off = 1; off < 1024; off <<= 1) {
        int v = (t >= off) ? ssum[t - off] : 0;
        __syncthreads();
        ssum[t] += v;
        __syncthreads();
    }
    int run = (t == 0) ? 0 : ssum[t - 1];
    for (int j = 0; j < CH; j++) {
        int idx = base + j;
        if (idx < N_NODES) { g_rowptr[idx] = run; g_cursor[idx] = run; run += g_deg[idx]; }
    }
    if (t == 1023) g_rowptr[N_NODES] = ssum[1023];
}
__global__ void k_scatter(const int* __restrict__ src, const int* __restrict__ dst) {
    int i = blockIdx.x * blockDim.x + threadIdx.x;
    if (i < E_EDGES) {
        int p = atomicAdd(&g_cursor[dst[i]], 1);
        g_esrc[p] = src[i];
    }
}

// ---------------- bf16 split helpers ----------------------------------------
__device__ __forceinline__ uint32_t pack_hi(float x, float y) {
    __nv_bfloat16 hx = __float2bfloat16(x), hy = __float2bfloat16(y);
    return ((uint32_t)__bfloat16_as_ushort(hy) << 16) | __bfloat16_as_ushort(hx);
}
__device__ __forceinline__ uint32_t pack_lo(float x, float y) {
    __nv_bfloat16 hx = __float2bfloat16(x), hy = __float2bfloat16(y);
    __nv_bfloat16 lx = __float2bfloat16(x - __bfloat162float(hx));
    __nv_bfloat16 ly = __float2bfloat16(y - __bfloat162float(hy));
    return ((uint32_t)__bfloat16_as_ushort(ly) << 16) | __bfloat16_as_ushort(lx);
}

__global__ void k_prepw(const float* __restrict__ wl, const float* __restrict__ wr,
                        uint32_t* __restrict__ hi, uint32_t* __restrict__ lo) {
    int i = blockIdx.x * blockDim.x + threadIdx.x;
    if (i >= 256 * 64) return;
    int n = i >> 6, p = i & 63;
    const float* wp = ((n < 128) ? wl : wr) + (size_t)(n & 127) * 128 + p * 2;
    float2 v = *(const float2*)wp;
    hi[i] = pack_hi(v.x, v.y);
    lo[i] = pack_lo(v.x, v.y);
}

__global__ void k_prepx(const float* __restrict__ X) {
    int i = blockIdx.x * blockDim.x + threadIdx.x;
    if (i >= N_NODES * 64) return;
    float2 v = *(const float2*)(X + (size_t)i * 2);
    g_xhi[i] = pack_hi(v.x, v.y);
    g_xlo[i] = pack_lo(v.x, v.y);
}

// ---------------- split-bf16 HMMA GEMM (R7 tile; fragment-reuse inner loop) --
#define LDP   136
#define LDPU  68
#define SMEM_AHI 0
#define SMEM_ALO (SMEM_AHI + 128 * LDP * 2)
#define SMEM_BHI (SMEM_ALO + 128 * LDP * 2)
#define SMEM_BLO (SMEM_BHI + 64 * LDP * 2)
#define SMEM_TOT (SMEM_BLO + 64 * LDP * 2)

__device__ __forceinline__ void ldsm4(uint32_t& r0, uint32_t& r1, uint32_t& r2,
                                      uint32_t& r3, uint32_t addr) {
    asm volatile("ldmatrix.sync.aligned.m8n8.x4.shared.b16 {%0,%1,%2,%3}, [%4];"
                 : "=r"(r0), "=r"(r1), "=r"(r2), "=r"(r3) : "r"(addr));
}
__device__ __forceinline__ void mma16816(float* c, const uint32_t* a, const uint32_t* b) {
    asm volatile(
        "mma.sync.aligned.m16n8k16.row.col.f32.bf16.bf16.f32 "
        "{%0,%1,%2,%3}, {%4,%5,%6,%7}, {%8,%9}, {%0,%1,%2,%3};"
        : "+f"(c[0]), "+f"(c[1]), "+f"(c[2]), "+f"(c[3])
        : "r"(a[0]), "r"(a[1]), "r"(a[2]), "r"(a[3]), "r"(b[0]), "r"(b[1]));
}

__global__ void __launch_bounds__(256, 2)
k_gemm_tc(const uint32_t* __restrict__ whi, const uint32_t* __restrict__ wlo) {
    extern __shared__ char smem[];
    const uint32_t sb = s2u(smem);
    const int tid  = threadIdx.x;
    const int warp = tid >> 5;
    const int lane = tid & 31;
    const int mblk = blockIdx.x >> 2;
    const int nblk = blockIdx.x & 3;

    // ---- stage A (2x 32KB, predicated) + B (2x 16KB) via cp.async ----
    for (int c = tid; c < 2048; c += 256) {
        int row = c >> 4, seg = c & 15;
        long grow = (long)mblk * 128 + row;
        int sz = (grow < N_NODES) ? 16 : 0;
        uint32_t doff = (uint32_t)(row * (LDP * 2) + seg * 16);
        size_t soff = (size_t)grow * 256 + seg * 16;
        cpasync16p(sb + SMEM_AHI + doff, (const char*)g_xhi + soff, sz);
        cpasync16p(sb + SMEM_ALO + doff, (const char*)g_xlo + soff, sz);
    }
    {
        const char* bh = (const char*)(whi + (size_t)nblk * 64 * 64);
        const char* bl = (const char*)(wlo + (size_t)nblk * 64 * 64);
        for (int c = tid; c < 1024; c += 256) {
            int row = c >> 4, seg = c & 15;
            uint32_t doff = (uint32_t)(row * (LDP * 2) + seg * 16);
            uint32_t soff = (uint32_t)(row * 256 + seg * 16);
            cpasync16(sb + SMEM_BHI + doff, bh + soff);
            cpasync16(sb + SMEM_BLO + doff, bl + soff);
        }
    }
    asm volatile("cp.async.commit_group;" ::: "memory");
    asm volatile("cp.async.wait_group 0;" ::: "memory");
    __syncthreads();

    // ---- compute: 8 warps as 4M x 2N, warp tile 32x32 ----
    // k0-outer with fragment reuse: 8 ldsm4/k0 instead of 12.
    //   load Ahi,Bhi -> MMA(Ahi,Bhi); load Alo -> MMA(Alo,Bhi);
    //   load Blo over Bhi -> MMA(Ahi,Blo).
    const int wm = (warp >> 1) * 32;
    const int wn = (warp & 1) * 32;
    float c[2][4][4];
#pragma unroll
    for (int mi = 0; mi < 2; mi++)
#pragma unroll
        for (int ni = 0; ni < 4; ni++)
#pragma unroll
            for (int q = 0; q < 4; q++) c[mi][ni][q] = 0.f;

    const uint32_t aRowOff = (uint32_t)((wm + (lane & 15)) * LDP + ((lane >> 4) << 3)) << 1;
    const uint32_t bRowOff = (uint32_t)((wn + ((lane >> 4) << 3) + (lane & 7)) * LDP
                                        + (((lane >> 3) & 1) << 3)) << 1;
    const uint32_t AhiB = sb + SMEM_AHI + aRowOff;
    const uint32_t AloB = sb + SMEM_ALO + aRowOff;
    const uint32_t BhiB = sb + SMEM_BHI + bRowOff;
    const uint32_t BloB = sb + SMEM_BLO + bRowOff;

#pragma unroll
    for (int k0 = 0; k0 < 128; k0 += 16) {
        const uint32_t ko = (uint32_t)(k0 << 1);
        uint32_t ahi[2][4], alo[2][4], b[4][2];

        // Ahi + Bhi
        ldsm4(ahi[0][0], ahi[0][1], ahi[0][2], ahi[0][3], AhiB + ko);
        ldsm4(ahi[1][0], ahi[1][1], ahi[1][2], ahi[1][3], AhiB + ((16 * LDP) << 1) + ko);
#pragma unroll
        for (int nq = 0; nq < 2; nq++) {
            uint32_t r0, r1, r2, r3;
            ldsm4(r0, r1, r2, r3, BhiB + ((nq * 16 * LDP) << 1) + ko);
            b[nq * 2][0] = r0; b[nq * 2][1] = r1;
            b[nq * 2 + 1][0] = r2; b[nq * 2 + 1][1] = r3;
        }
#pragma unroll
        for (int mi = 0; mi < 2; mi++)
#pragma unroll
            for (int ni = 0; ni < 4; ni++)
                mma16816(c[mi][ni], ahi[mi], b[ni]);      // Ahi * Bhi

        // Alo (reuse Bhi fragments)
        ldsm4(alo[0][0], alo[0][1], alo[0][2], alo[0][3], AloB + ko);
        ldsm4(alo[1][0], alo[1][1], alo[1][2], alo[1][3], AloB + ((16 * LDP) << 1) + ko);
#pragma unroll
        for (int mi = 0; mi < 2; mi++)
#pragma unroll
            for (int ni = 0; ni < 4; ni++)
                mma16816(c[mi][ni], alo[mi], b[ni]);      // Alo * Bhi

        // Blo over Bhi storage (reuse Ahi fragments)
#pragma unroll
        for (int nq = 0; nq < 2; nq++) {
            uint32_t r0, r1, r2, r3;
            ldsm4(r0, r1, r2, r3, BloB + ((nq * 16 * LDP) << 1) + ko);
            b[nq * 2][0] = r0; b[nq * 2][1] = r1;
            b[nq * 2 + 1][0] = r2; b[nq * 2 + 1][1] = r3;
        }
#pragma unroll
        for (int mi = 0; mi < 2; mi++)
#pragma unroll
            for (int ni = 0; ni < 4; ni++)
                mma16816(c[mi][ni], ahi[mi], b[ni]);      // Ahi * Blo
    }

    // ---- epilogue (R7-exact) ----
    float* buf = (nblk < 2) ? g_xl : g_xr;
    const int colbase = ((nblk * 64) & 127) + wn + (lane & 3) * 2;
#pragma unroll
    for (int mi = 0; mi < 2; mi++) {
#pragma unroll
        for (int half = 0; half < 2; half++) {
            long row = (long)mblk * 128 + wm + mi * 16 + (lane >> 2) + half * 8;
            if (row >= N_NODES) continue;
            float* rp = buf + row * HID + colbase;
#pragma unroll
            for (int ni = 0; ni < 4; ni++) {
                float2 v = make_float2(c[mi][ni][half * 2], c[mi][ni][half * 2 + 1]);
                *(float2*)(rp + ni * 8) = v;
            }
        }
    }
}

// ---------------- fused per-node attention (R7-exact) -----------------------
template <int LAYER>
__global__ void k_node(const float* __restrict__ att, const float* __restrict__ b,
                       float* __restrict__ outbuf) {
    const int n    = (blockIdx.x * blockDim.x + threadIdx.x) >> 5;
    const int lane = threadIdx.x & 31;
    if (n >= N_NODES) return;

    const int beg = g_rowptr[n];
    const int end = g_rowptr[n + 1];

    const float4 xr = *(const float4*)(g_xr + (size_t)n * HID + lane * 4);
    const float4 at = *(const float4*)(att + lane * 4);

    float4 acc = make_float4(0.f, 0.f, 0.f, 0.f);
    float  sum = 0.f;

    for (int i0 = beg; i0 < end; i0 += 32) {
        const int cnt = min(32, end - i0);
        int sid = (lane < cnt) ? g_esrc[i0 + lane] : 0;
        for (int j = 0; j < cnt; j++) {
            const int s = __shfl_sync(0xffffffffu, sid, j);
            const float4 xl = *(const float4*)(g_xl + (size_t)s * HID + lane * 4);
            float p = lrelu(xl.x + xr.x, ATT_SLOPE) * at.x
                    + lrelu(xl.y + xr.y, ATT_SLOPE) * at.y
                    + lrelu(xl.z + xr.z, ATT_SLOPE) * at.z
                    + lrelu(xl.w + xr.w, ATT_SLOPE) * at.w;
            p += __shfl_xor_sync(0xffffffffu, p, 8);
            p += __shfl_xor_sync(0xffffffffu, p, 4);
            p += __shfl_xor_sync(0xffffffffu, p, 2);
            p += __shfl_xor_sync(0xffffffffu, p, 1);
            const float ex = __expf(p);
            sum += ex;
            acc.x = fmaf(ex, xl.x, acc.x);
            acc.y = fmaf(ex, xl.y, acc.y);
            acc.z = fmaf(ex, xl.z, acc.z);
            acc.w = fmaf(ex, xl.w, acc.w);
        }
    }

    const float inv = 1.f / (sum + 1e-16f);
    const float4 bb = *(const float4*)(b + lane * 4);
    float4 o;
    o.x = fmaf(acc.x, inv, bb.x);
    o.y = fmaf(acc.y, inv, bb.y);
    o.z = fmaf(acc.z, inv, bb.z);
    o.w = fmaf(acc.w, inv, bb.w);

    float* dstp = outbuf + (size_t)n * HID + lane * 4;
    if (LAYER == 1) {
        o.x = lrelu(o.x, OUT_SLOPE);
        o.y = lrelu(o.y, OUT_SLOPE);
        o.z = lrelu(o.z, OUT_SLOPE);
        o.w = lrelu(o.w, OUT_SLOPE);
        *(float4*)dstp = o;
        const size_t ib = (size_t)n * 64 + lane * 2;
        uint2 hi = make_uint2(pack_hi(o.x, o.y), pack_hi(o.z, o.w));
        uint2 lo = make_uint2(pack_lo(o.x, o.y), pack_lo(o.z, o.w));
        *(uint2*)(g_xhi + ib) = hi;
        *(uint2*)(g_xlo + ib) = lo;
    } else {
        const float4 h = *(const float4*)(g_h1 + (size_t)n * HID + lane * 4);
        o.x += h.x; o.y += h.y; o.z += h.z; o.w += h.w;
        *(float4*)dstp = o;
    }
}

// ---------------- launch (R7-exact schedule) ---------------------------------
extern "C" void kernel_launch(void* const* d_in, const int* in_sizes, int n_in,
                              void* d_out, int out_size) {
    const float* x    = (const float*)d_in[0];
    const int*   ei   = (const int*)d_in[1];
    const float* wl1  = (const float*)d_in[2];
    const float* wr1  = (const float*)d_in[3];
    const float* att1 = (const float*)d_in[4];
    const float* b1   = (const float*)d_in[5];
    const float* wl2  = (const float*)d_in[6];
    const float* wr2  = (const float*)d_in[7];
    const float* att2 = (const float*)d_in[8];
    const float* b2   = (const float*)d_in[9];
    float* out = (float*)d_out;

    const int* src = ei;
    const int* dst = ei + E_EDGES;

    void* h1_ptr = nullptr;
    cudaGetSymbolAddress(&h1_ptr, g_h1);
    void *w1hi, *w1lo, *w2hi, *w2lo;
    cudaGetSymbolAddress(&w1hi, g_w1hi);
    cudaGetSymbolAddress(&w1lo, g_w1lo);
    cudaGetSymbolAddress(&w2hi, g_w2hi);
    cudaGetSymbolAddress(&w2lo, g_w2lo);

    static cudaStream_t s1 = nullptr;
    static cudaEvent_t ev_fork = nullptr, ev_csr = nullptr;
    if (s1 == nullptr) {
        cudaStreamCreateWithFlags(&s1, cudaStreamNonBlocking);
        cudaEventCreateWithFlags(&ev_fork, cudaEventDisableTiming);
        cudaEventCreateWithFlags(&ev_csr, cudaEventDisableTiming);
    }

    cudaFuncSetAttribute(k_gemm_tc, cudaFuncAttributeMaxDynamicSharedMemorySize, SMEM_TOT);

    const int gemm_blocks = ((N_NODES + 127) / 128) * 4;    // 1564
    const int node_blocks = (N_NODES * 32 + 255) / 256;     // 6250
    const int e_blocks = (E_EDGES + 255) / 256;
    const int n_blocks = (N_NODES + 255) / 256;
    const int w_blocks = (256 * 64 + 255) / 256;
    const int px_blocks = (N_NODES * 64 + 255) / 256;

    // s0: prepw1, prepx, gemm1 (slot 4), node1, gemm2, node2
    // s1 (forked): prepw2 + CSR build — hidden behind gemm1
    k_prepw<<<w_blocks, 256>>>(wl1, wr1, (uint32_t*)w1hi, (uint32_t*)w1lo);
    k_prepx<<<px_blocks, 256>>>(x);

    cudaEventRecord(ev_fork, 0);
    cudaStreamWaitEvent(s1, ev_fork, 0);
    k_prepw<<<w_blocks, 256, 0, s1>>>(wl2, wr2, (uint32_t*)w2hi, (uint32_t*)w2lo);

    k_gemm_tc<<<gemm_blocks, 256, SMEM_TOT>>>((const uint32_t*)w1hi, (const uint32_t*)w1lo);

    k_zero_deg<<<n_blocks, 256, 0, s1>>>();
    k_hist<<<e_blocks, 256, 0, s1>>>(dst);
    k_scan<<<1, 1024, 0, s1>>>();
    k_scatter<<<e_blocks, 256, 0, s1>>>(src, dst);
    cudaEventRecord(ev_csr, s1);
    cudaStreamWaitEvent(0, ev_csr, 0);

    k_node<1><<<node_blocks, 256>>>(att1, b1, (float*)h1_ptr);
    k_gemm_tc<<<gemm_blocks, 256, SMEM_TOT>>>((const uint32_t*)w2hi, (const uint32_t*)w2lo);
    k_node<2><<<node_blocks, 256>>>(att2, b2, out);
}

// round 15
// speedup vs baseline: 1.6892x; 1.0472x over previous
#include <cuda_runtime.h>
#include <cuda_bf16.h>
#include <math_constants.h>
#include <cstdint>

#define N_NODES 50000
#define HID     128
#define E_EDGES 640000
#define ATT_SLOPE 0.2f
#define OUT_SLOPE 0.01f

// ---------------- scratch (device globals; no allocation allowed) ----------
__device__ float g_xl[N_NODES * HID];
__device__ float g_xr[N_NODES * HID];
__device__ float g_h1[N_NODES * HID];
__device__ int   g_deg[N_NODES];
__device__ int   g_rowptr[N_NODES + 1];
__device__ int   g_cursor[N_NODES];
__device__ int   g_esrc[E_EDGES];
__device__ uint32_t g_xhi[N_NODES * 64];
__device__ uint32_t g_xlo[N_NODES * 64];
__device__ uint32_t g_w1hi[256 * 64];
__device__ uint32_t g_w1lo[256 * 64];
__device__ uint32_t g_w2hi[256 * 64];
__device__ uint32_t g_w2lo[256 * 64];

__device__ __forceinline__ float lrelu(float x, float s) { return x > 0.f ? x : s * x; }

__device__ __forceinline__ uint32_t s2u(const void* p) {
    uint32_t a;
    asm("{ .reg .u64 t; cvta.to.shared.u64 t, %1; cvt.u32.u64 %0, t; }" : "=r"(a) : "l"(p));
    return a;
}
__device__ __forceinline__ void cpasync16(uint32_t dst, const void* src) {
    asm volatile("cp.async.cg.shared.global [%0], [%1], 16;" :: "r"(dst), "l"(src));
}
__device__ __forceinline__ void cpasync16p(uint32_t dst, const void* src, int sz) {
    asm volatile("cp.async.cg.shared.global [%0], [%1], 16, %2;"
                 :: "r"(dst), "l"(src), "r"(sz));
}

// ---------------- CSR build (R7-exact) ---------------------------------------
__global__ void k_zero_deg() {
    int i = blockIdx.x * blockDim.x + threadIdx.x;
    if (i < N_NODES) g_deg[i] = 0;
}
__global__ void k_hist(const int* __restrict__ dst) {
    int i = blockIdx.x * blockDim.x + threadIdx.x;
    if (i < E_EDGES) atomicAdd(&g_deg[dst[i]], 1);
}
__global__ void __launch_bounds__(1024) k_scan() {
    __shared__ int ssum[1024];
    const int t = threadIdx.x;
    const int CH = (N_NODES + 1023) / 1024;
    const int base = t * CH;
    int s = 0;
    for (int j = 0; j < CH; j++) { int idx = base + j; if (idx < N_NODES) s += g_deg[idx]; }
    ssum[t] = s;
    __syncthreads();
    for (int off = 1; off < 1024; off <<= 1) {
        int v = (t >= off) ? ssum[t - off] : 0;
        __syncthreads();
        ssum[t] += v;
        __syncthreads();
    }
    int run = (t == 0) ? 0 : ssum[t - 1];
    for (int j = 0; j < CH; j++) {
        int idx = base + j;
        if (idx < N_NODES) { g_rowptr[idx] = run; g_cursor[idx] = run; run += g_deg[idx]; }
    }
    if (t == 1023) g_rowptr[N_NODES] = ssum[1023];
}
__global__ void k_scatter(const int* __restrict__ src, const int* __restrict__ dst) {
    int i = blockIdx.x * blockDim.x + threadIdx.x;
    if (i < E_EDGES) {
        int p = atomicAdd(&g_cursor[dst[i]], 1);
        g_esrc[p] = src[i];
    }
}

// ---------------- bf16 split helpers ----------------------------------------
__device__ __forceinline__ uint32_t pack_hi(float x, float y) {
    __nv_bfloat16 hx = __float2bfloat16(x), hy = __float2bfloat16(y);
    return ((uint32_t)__bfloat16_as_ushort(hy) << 16) | __bfloat16_as_ushort(hx);
}
__device__ __forceinline__ uint32_t pack_lo(float x, float y) {
    __nv_bfloat16 hx = __float2bfloat16(x), hy = __float2bfloat16(y);
    __nv_bfloat16 lx = __float2bfloat16(x - __bfloat162float(hx));
    __nv_bfloat16 ly = __float2bfloat16(y - __bfloat162float(hy));
    return ((uint32_t)__bfloat16_as_ushort(ly) << 16) | __bfloat16_as_ushort(lx);
}

__global__ void k_prepw(const float* __restrict__ wl, const float* __restrict__ wr,
                        uint32_t* __restrict__ hi, uint32_t* __restrict__ lo) {
    int i = blockIdx.x * blockDim.x + threadIdx.x;
    if (i >= 256 * 64) return;
    int n = i >> 6, p = i & 63;
    const float* wp = ((n < 128) ? wl : wr) + (size_t)(n & 127) * 128 + p * 2;
    float2 v = *(const float2*)wp;
    hi[i] = pack_hi(v.x, v.y);
    lo[i] = pack_lo(v.x, v.y);
}

__global__ void k_prepx(const float* __restrict__ X) {
    int i = blockIdx.x * blockDim.x + threadIdx.x;
    if (i >= N_NODES * 64) return;
    float2 v = *(const float2*)(X + (size_t)i * 2);
    g_xhi[i] = pack_hi(v.x, v.y);
    g_xlo[i] = pack_lo(v.x, v.y);
}

// ---------------- split-bf16 HMMA GEMM (R14 + K-split double-buffered stage) -
#define LDP   136
#define LDPU  68
#define SMEM_AHI 0
#define SMEM_ALO (SMEM_AHI + 128 * LDP * 2)
#define SMEM_BHI (SMEM_ALO + 128 * LDP * 2)
#define SMEM_BLO (SMEM_BHI + 64 * LDP * 2)
#define SMEM_TOT (SMEM_BLO + 64 * LDP * 2)

__device__ __forceinline__ void ldsm4(uint32_t& r0, uint32_t& r1, uint32_t& r2,
                                      uint32_t& r3, uint32_t addr) {
    asm volatile("ldmatrix.sync.aligned.m8n8.x4.shared.b16 {%0,%1,%2,%3}, [%4];"
                 : "=r"(r0), "=r"(r1), "=r"(r2), "=r"(r3) : "r"(addr));
}
__device__ __forceinline__ void mma16816(float* c, const uint32_t* a, const uint32_t* b) {
    asm volatile(
        "mma.sync.aligned.m16n8k16.row.col.f32.bf16.bf16.f32 "
        "{%0,%1,%2,%3}, {%4,%5,%6,%7}, {%8,%9}, {%0,%1,%2,%3};"
        : "+f"(c[0]), "+f"(c[1]), "+f"(c[2]), "+f"(c[3])
        : "r"(a[0]), "r"(a[1]), "r"(a[2]), "r"(a[3]), "r"(b[0]), "r"(b[1]));
}

__global__ void __launch_bounds__(256, 2)
k_gemm_tc(const uint32_t* __restrict__ whi, const uint32_t* __restrict__ wlo) {
    extern __shared__ char smem[];
    const uint32_t sb = s2u(smem);
    const int tid  = threadIdx.x;
    const int warp = tid >> 5;
    const int lane = tid & 31;
    const int mblk = blockIdx.x >> 2;
    const int nblk = blockIdx.x & 3;

    // ---- group 1: B full (hi+lo) + A k-cols [0,64) (hi+lo) ----
    {
        const char* bh = (const char*)(whi + (size_t)nblk * 64 * 64);
        const char* bl = (const char*)(wlo + (size_t)nblk * 64 * 64);
        for (int c = tid; c < 1024; c += 256) {
            int row = c >> 4, seg = c & 15;
            uint32_t doff = (uint32_t)(row * (LDP * 2) + seg * 16);
            uint32_t soff = (uint32_t)(row * 256 + seg * 16);
            cpasync16(sb + SMEM_BHI + doff, bh + soff);
            cpasync16(sb + SMEM_BLO + doff, bl + soff);
        }
    }
    for (int c = tid; c < 1024; c += 256) {
        int row = c >> 3, seg = c & 7;                    // segs 0..7 = k-cols 0..63
        long grow = (long)mblk * 128 + row;
        int sz = (grow < N_NODES) ? 16 : 0;
        uint32_t doff = (uint32_t)(row * (LDP * 2) + seg * 16);
        size_t soff = (size_t)grow * 256 + seg * 16;
        cpasync16p(sb + SMEM_AHI + doff, (const char*)g_xhi + soff, sz);
        cpasync16p(sb + SMEM_ALO + doff, (const char*)g_xlo + soff, sz);
    }
    asm volatile("cp.async.commit_group;" ::: "memory");

    // ---- group 2: A k-cols [64,128) (hi+lo) ----
    for (int c = tid; c < 1024; c += 256) {
        int row = c >> 3, seg = (c & 7) + 8;              // segs 8..15 = k-cols 64..127
        long grow = (long)mblk * 128 + row;
        int sz = (grow < N_NODES) ? 16 : 0;
        uint32_t doff = (uint32_t)(row * (LDP * 2) + seg * 16);
        size_t soff = (size_t)grow * 256 + seg * 16;
        cpasync16p(sb + SMEM_AHI + doff, (const char*)g_xhi + soff, sz);
        cpasync16p(sb + SMEM_ALO + doff, (const char*)g_xlo + soff, sz);
    }
    asm volatile("cp.async.commit_group;" ::: "memory");

    // ---- wait for group 1 only (group 2 still in flight) ----
    asm volatile("cp.async.wait_group 1;" ::: "memory");
    __syncthreads();

    const int wm = (warp >> 1) * 32;
    const int wn = (warp & 1) * 32;
    float c[2][4][4];
#pragma unroll
    for (int mi = 0; mi < 2; mi++)
#pragma unroll
        for (int ni = 0; ni < 4; ni++)
#pragma unroll
            for (int q = 0; q < 4; q++) c[mi][ni][q] = 0.f;

    const uint32_t aRowOff = (uint32_t)((wm + (lane & 15)) * LDP + ((lane >> 4) << 3)) << 1;
    const uint32_t bRowOff = (uint32_t)((wn + ((lane >> 4) << 3) + (lane & 7)) * LDP
                                        + (((lane >> 3) & 1) << 3)) << 1;
    const uint32_t AhiB = sb + SMEM_AHI + aRowOff;
    const uint32_t AloB = sb + SMEM_ALO + aRowOff;
    const uint32_t BhiB = sb + SMEM_BHI + bRowOff;
    const uint32_t BloB = sb + SMEM_BLO + bRowOff;

#pragma unroll
    for (int half = 0; half < 2; half++) {
        if (half == 1) {
            // second A half must have landed
            asm volatile("cp.async.wait_group 0;" ::: "memory");
            __syncthreads();
        }
#pragma unroll
        for (int kq = 0; kq < 4; kq++) {
            const int k0 = half * 64 + kq * 16;
            const uint32_t ko = (uint32_t)(k0 << 1);
            uint32_t ahi[2][4], alo[2][4], b[4][2];

            // Ahi + Bhi
            ldsm4(ahi[0][0], ahi[0][1], ahi[0][2], ahi[0][3], AhiB + ko);
            ldsm4(ahi[1][0], ahi[1][1], ahi[1][2], ahi[1][3], AhiB + ((16 * LDP) << 1) + ko);
#pragma unroll
            for (int nq = 0; nq < 2; nq++) {
                uint32_t r0, r1, r2, r3;
                ldsm4(r0, r1, r2, r3, BhiB + ((nq * 16 * LDP) << 1) + ko);
                b[nq * 2][0] = r0; b[nq * 2][1] = r1;
                b[nq * 2 + 1][0] = r2; b[nq * 2 + 1][1] = r3;
            }
#pragma unroll
            for (int mi = 0; mi < 2; mi++)
#pragma unroll
                for (int ni = 0; ni < 4; ni++)
                    mma16816(c[mi][ni], ahi[mi], b[ni]);      // Ahi * Bhi

            // Alo (reuse Bhi fragments)
            ldsm4(alo[0][0], alo[0][1], alo[0][2], alo[0][3], AloB + ko);
            ldsm4(alo[1][0], alo[1][1], alo[1][2], alo[1][3], AloB + ((16 * LDP) << 1) + ko);
#pragma unroll
            for (int mi = 0; mi < 2; mi++)
#pragma unroll
                for (int ni = 0; ni < 4; ni++)
                    mma16816(c[mi][ni], alo[mi], b[ni]);      // Alo * Bhi

            // Blo over Bhi registers (reuse Ahi fragments)
#pragma unroll
            for (int nq = 0; nq < 2; nq++) {
                uint32_t r0, r1, r2, r3;
                ldsm4(r0, r1, r2, r3, BloB + ((nq * 16 * LDP) << 1) + ko);
                b[nq * 2][0] = r0; b[nq * 2][1] = r1;
                b[nq * 2 + 1][0] = r2; b[nq * 2 + 1][1] = r3;
            }
#pragma unroll
            for (int mi = 0; mi < 2; mi++)
#pragma unroll
                for (int ni = 0; ni < 4; ni++)
                    mma16816(c[mi][ni], ahi[mi], b[ni]);      // Ahi * Blo
        }
    }

    // ---- epilogue (R7-exact) ----
    float* buf = (nblk < 2) ? g_xl : g_xr;
    const int colbase = ((nblk * 64) & 127) + wn + (lane & 3) * 2;
#pragma unroll
    for (int mi = 0; mi < 2; mi++) {
#pragma unroll
        for (int half = 0; half < 2; half++) {
            long row = (long)mblk * 128 + wm + mi * 16 + (lane >> 2) + half * 8;
            if (row >= N_NODES) continue;
            float* rp = buf + row * HID + colbase;
#pragma unroll
            for (int ni = 0; ni < 4; ni++) {
                float2 v = make_float2(c[mi][ni][half * 2], c[mi][ni][half * 2 + 1]);
                *(float2*)(rp + ni * 8) = v;
            }
        }
    }
}

// ---------------- fused per-node attention (R7-exact) -----------------------
template <int LAYER>
__global__ void k_node(const float* __restrict__ att, const float* __restrict__ b,
                       float* __restrict__ outbuf) {
    const int n    = (blockIdx.x * blockDim.x + threadIdx.x) >> 5;
    const int lane = threadIdx.x & 31;
    if (n >= N_NODES) return;

    const int beg = g_rowptr[n];
    const int end = g_rowptr[n + 1];

    const float4 xr = *(const float4*)(g_xr + (size_t)n * HID + lane * 4);
    const float4 at = *(const float4*)(att + lane * 4);

    float4 acc = make_float4(0.f, 0.f, 0.f, 0.f);
    float  sum = 0.f;

    for (int i0 = beg; i0 < end; i0 += 32) {
        const int cnt = min(32, end - i0);
        int sid = (lane < cnt) ? g_esrc[i0 + lane] : 0;
        for (int j = 0; j < cnt; j++) {
            const int s = __shfl_sync(0xffffffffu, sid, j);
            const float4 xl = *(const float4*)(g_xl + (size_t)s * HID + lane * 4);
            float p = lrelu(xl.x + xr.x, ATT_SLOPE) * at.x
                    + lrelu(xl.y + xr.y, ATT_SLOPE) * at.y
                    + lrelu(xl.z + xr.z, ATT_SLOPE) * at.z
                    + lrelu(xl.w + xr.w, ATT_SLOPE) * at.w;
            p += __shfl_xor_sync(0xffffffffu, p, 8);
            p += __shfl_xor_sync(0xffffffffu, p, 4);
            p += __shfl_xor_sync(0xffffffffu, p, 2);
            p += __shfl_xor_sync(0xffffffffu, p, 1);
            const float ex = __expf(p);
            sum += ex;
            acc.x = fmaf(ex, xl.x, acc.x);
            acc.y = fmaf(ex, xl.y, acc.y);
            acc.z = fmaf(ex, xl.z, acc.z);
            acc.w = fmaf(ex, xl.w, acc.w);
        }
    }

    const float inv = 1.f / (sum + 1e-16f);
    const float4 bb = *(const float4*)(b + lane * 4);
    float4 o;
    o.x = fmaf(acc.x, inv, bb.x);
    o.y = fmaf(acc.y, inv, bb.y);
    o.z = fmaf(acc.z, inv, bb.z);
    o.w = fmaf(acc.w, inv, bb.w);

    float* dstp = outbuf + (size_t)n * HID + lane * 4;
    if (LAYER == 1) {
        o.x = lrelu(o.x, OUT_SLOPE);
        o.y = lrelu(o.y, OUT_SLOPE);
        o.z = lrelu(o.z, OUT_SLOPE);
        o.w = lrelu(o.w, OUT_SLOPE);
        *(float4*)dstp = o;
        const size_t ib = (size_t)n * 64 + lane * 2;
        uint2 hi = make_uint2(pack_hi(o.x, o.y), pack_hi(o.z, o.w));
        uint2 lo = make_uint2(pack_lo(o.x, o.y), pack_lo(o.z, o.w));
        *(uint2*)(g_xhi + ib) = hi;
        *(uint2*)(g_xlo + ib) = lo;
    } else {
        const float4 h = *(const float4*)(g_h1 + (size_t)n * HID + lane * 4);
        o.x += h.x; o.y += h.y; o.z += h.z; o.w += h.w;
        *(float4*)dstp = o;
    }
}

// ---------------- launch (R7-exact schedule) ---------------------------------
extern "C" void kernel_launch(void* const* d_in, const int* in_sizes, int n_in,
                              void* d_out, int out_size) {
    const float* x    = (const float*)d_in[0];
    const int*   ei   = (const int*)d_in[1];
    const float* wl1  = (const float*)d_in[2];
    const float* wr1  = (const float*)d_in[3];
    const float* att1 = (const float*)d_in[4];
    const float* b1   = (const float*)d_in[5];
    const float* wl2  = (const float*)d_in[6];
    const float* wr2  = (const float*)d_in[7];
    const float* att2 = (const float*)d_in[8];
    const float* b2   = (const float*)d_in[9];
    float* out = (float*)d_out;

    const int* src = ei;
    const int* dst = ei + E_EDGES;

    void* h1_ptr = nullptr;
    cudaGetSymbolAddress(&h1_ptr, g_h1);
    void *w1hi, *w1lo, *w2hi, *w2lo;
    cudaGetSymbolAddress(&w1hi, g_w1hi);
    cudaGetSymbolAddress(&w1lo, g_w1lo);
    cudaGetSymbolAddress(&w2hi, g_w2hi);
    cudaGetSymbolAddress(&w2lo, g_w2lo);

    static cudaStream_t s1 = nullptr;
    static cudaEvent_t ev_fork = nullptr, ev_csr = nullptr;
    if (s1 == nullptr) {
        cudaStreamCreateWithFlags(&s1, cudaStreamNonBlocking);
        cudaEventCreateWithFlags(&ev_fork, cudaEventDisableTiming);
        cudaEventCreateWithFlags(&ev_csr, cudaEventDisableTiming);
    }

    cudaFuncSetAttribute(k_gemm_tc, cudaFuncAttributeMaxDynamicSharedMemorySize, SMEM_TOT);

    const int gemm_blocks = ((N_NODES + 127) / 128) * 4;    // 1564
    const int node_blocks = (N_NODES * 32 + 255) / 256;     // 6250
    const int e_blocks = (E_EDGES + 255) / 256;
    const int n_blocks = (N_NODES + 255) / 256;
    const int w_blocks = (256 * 64 + 255) / 256;
    const int px_blocks = (N_NODES * 64 + 255) / 256;

    // s0: prepw1, prepx, gemm1 (slot 4), node1, gemm2, node2
    // s1 (forked): prepw2 + CSR build — hidden behind gemm1
    k_prepw<<<w_blocks, 256>>>(wl1, wr1, (uint32_t*)w1hi, (uint32_t*)w1lo);
    k_prepx<<<px_blocks, 256>>>(x);

    cudaEventRecord(ev_fork, 0);
    cudaStreamWaitEvent(s1, ev_fork, 0);
    k_prepw<<<w_blocks, 256, 0, s1>>>(wl2, wr2, (uint32_t*)w2hi, (uint32_t*)w2lo);

    k_gemm_tc<<<gemm_blocks, 256, SMEM_TOT>>>((const uint32_t*)w1hi, (const uint32_t*)w1lo);

    k_zero_deg<<<n_blocks, 256, 0, s1>>>();
    k_hist<<<e_blocks, 256, 0, s1>>>(dst);
    k_scan<<<1, 1024, 0, s1>>>();
    k_scatter<<<e_blocks, 256, 0, s1>>>(src, dst);
    cudaEventRecord(ev_csr, s1);
    cudaStreamWaitEvent(0, ev_csr, 0);

    k_node<1><<<node_blocks, 256>>>(att1, b1, (float*)h1_ptr);
    k_gemm_tc<<<gemm_blocks, 256, SMEM_TOT>>>((const uint32_t*)w2hi, (const uint32_t*)w2lo);
    k_node<2><<<node_blocks, 256>>>(att2, b2, out);
}